// round 10
// baseline (speedup 1.0000x reference)
#include <cuda_runtime.h>
#include <cuda_bf16.h>
#include <math.h>

#define Tn   2048
#define Cn   2048
#define Nfused 3584

#define OFF_W 0
#define OFF_A (2048*96)
#define OFF_V (OFF_A + 2048*96)
#define OFF_G (OFF_V + 2048*64)

// scratch (device globals zero-initialized; scanned streams padded +8 rows)
__device__ float g_bigB[Nfused*Cn];
__device__ float g_bigBias[Nfused];
__device__ float g_B2[2048*512];
__device__ float g_h1act[Tn*512];
__device__ float g_xc[Tn*Cn];
__device__ float g_owc[Cn*Cn];
__device__ float g_qkvh[Tn*Nfused];
__device__ float g_wdec[(Tn+8)*Cn];
__device__ float g_iclr[Tn*Cn];
__device__ float g_ab  [(Tn+8)*Cn];
__device__ float g_vsig[Tn*Cn];
__device__ float g_gate[Tn*Cn];
__device__ float g_rrot[(Tn+8)*Cn];
__device__ float g_kfin[(Tn+8)*Cn];
__device__ float g_vfin[(Tn+8)*Cn];
__device__ float g_kk  [(Tn+8)*Cn];
__device__ float g_y[Tn*Cn];
__device__ float g_z[Tn*Cn];

__device__ __forceinline__ float sigf(float x){ return 1.0f/(1.0f + expf(-x)); }
__device__ __forceinline__ float decay_fn(float v){
    float nv = -v;
    float sp = (nv > 20.0f) ? nv : log1pf(expf(nv));
    return expf(-expf(-sp - 0.5f));
}
__device__ __forceinline__ float f2tf32f(float f){
    unsigned u;
    asm("cvt.rna.tf32.f32 %0, %1;" : "=r"(u) : "f"(f));
    return __uint_as_float(u);
}

#define CP16(sm, gp) asm volatile("cp.async.cg.shared.global [%0], [%1], 16;\n" :: "r"(sm), "l"(gp) : "memory")
#define CPCOMMIT()   asm volatile("cp.async.commit_group;\n" ::)
#define CPWAIT(n)    asm volatile("cp.async.wait_group %0;\n" :: "n"(n) : "memory")

__device__ __forceinline__ int SW(int row, int col){
    return row*16 + (col ^ (4*((row>>1)&3)));
}

// ---------------- pipelined TF32 GEMM body (operands pre-truncated to tf32) ----------------
// epi: 0 none, 3 sigmoid(c+bias), 4 decay(c+bias)
__device__ __forceinline__ void gemm_body(
    const float* __restrict__ A, int lda, const float* __restrict__ B,
    const float* __restrict__ bias, float* __restrict__ C, int N, int K, int epi)
{
    __shared__ float As[3][128*16];
    __shared__ float Bs[3][128*16];
    const int m0 = blockIdx.y*128, n0 = blockIdx.x*128;
    const int tid = threadIdx.x;
    const int wid = tid>>5, lane = tid&31;
    const int wm = (wid>>1)*32, wn = (wid&1)*64;
    const int r = lane>>2, q = lane&3;

    const int row0 = tid>>2, c40 = (tid&3)*4;
    const int row1 = row0 + 64;
    const float* Ag = A + (size_t)m0*lda;
    const float* Bg = B + (size_t)n0*K;
    const size_t a0off = (size_t)row0*lda + c40;
    const size_t a1off = (size_t)row1*lda + c40;
    const size_t b0off = (size_t)row0*K + c40;
    const size_t b1off = (size_t)row1*K + c40;

    float acc[2][8][4];
    #pragma unroll
    for (int i=0;i<2;i++)
        #pragma unroll
        for (int j=0;j<8;j++)
            #pragma unroll
            for (int c=0;c<4;c++) acc[i][j][c]=0.f;

    const int niter = K/16;
    #pragma unroll
    for (int p=0;p<2;p++){
        unsigned sa = (unsigned)__cvta_generic_to_shared(&As[p][0]);
        unsigned sb = (unsigned)__cvta_generic_to_shared(&Bs[p][0]);
        CP16(sa + SW(row0,c40)*4, Ag + p*16 + a0off);
        CP16(sa + SW(row1,c40)*4, Ag + p*16 + a1off);
        CP16(sb + SW(row0,c40)*4, Bg + p*16 + b0off);
        CP16(sb + SW(row1,c40)*4, Bg + p*16 + b1off);
        CPCOMMIT();
    }

    for (int it=0; it<niter; it++){
        const int nx = it+2;
        if (nx < niter){
            const int buf = nx%3;
            unsigned sa = (unsigned)__cvta_generic_to_shared(&As[buf][0]);
            unsigned sb = (unsigned)__cvta_generic_to_shared(&Bs[buf][0]);
            CP16(sa + SW(row0,c40)*4, Ag + nx*16 + a0off);
            CP16(sa + SW(row1,c40)*4, Ag + nx*16 + a1off);
            CP16(sb + SW(row0,c40)*4, Bg + nx*16 + b0off);
            CP16(sb + SW(row1,c40)*4, Bg + nx*16 + b1off);
        }
        CPCOMMIT();
        CPWAIT(2);
        __syncthreads();
        const float* as = As[it%3];
        const float* bs = Bs[it%3];
        #pragma unroll
        for (int ks=0; ks<2; ks++){
            const int kk = ks*8;
            unsigned a[2][4], b[8][2];
            #pragma unroll
            for (int mt=0;mt<2;mt++){
                const int row = wm + mt*16;
                a[mt][0]=__float_as_uint(as[SW(row+r,  kk+q  )]);
                a[mt][1]=__float_as_uint(as[SW(row+r+8,kk+q  )]);
                a[mt][2]=__float_as_uint(as[SW(row+r,  kk+q+4)]);
                a[mt][3]=__float_as_uint(as[SW(row+r+8,kk+q+4)]);
            }
            #pragma unroll
            for (int nt=0;nt<8;nt++){
                const int col = wn + nt*8;
                b[nt][0]=__float_as_uint(bs[SW(col+r, kk+q  )]);
                b[nt][1]=__float_as_uint(bs[SW(col+r, kk+q+4)]);
            }
            #pragma unroll
            for (int mt=0;mt<2;mt++){
                #pragma unroll
                for (int nt=0;nt<8;nt++){
                    asm volatile(
                        "mma.sync.aligned.m16n8k8.row.col.f32.tf32.tf32.f32 "
                        "{%0,%1,%2,%3}, {%4,%5,%6,%7}, {%8,%9}, {%0,%1,%2,%3};"
                        : "+f"(acc[mt][nt][0]),"+f"(acc[mt][nt][1]),
                          "+f"(acc[mt][nt][2]),"+f"(acc[mt][nt][3])
                        : "r"(a[mt][0]),"r"(a[mt][1]),"r"(a[mt][2]),"r"(a[mt][3]),
                          "r"(b[nt][0]),"r"(b[nt][1]));
                }
            }
        }
        __syncthreads();
    }
    #pragma unroll
    for (int mt=0;mt<2;mt++){
        #pragma unroll
        for (int nt=0;nt<8;nt++){
            int row = m0 + wm + mt*16 + r;
            int col = n0 + wn + nt*8 + q*2;
            float bx=0.f, by=0.f;
            if (bias){ bx=bias[col]; by=bias[col+1]; }
            float o00=acc[mt][nt][0]+bx, o01=acc[mt][nt][1]+by;
            float o10=acc[mt][nt][2]+bx, o11=acc[mt][nt][3]+by;
            if (epi==3){ o00=sigf(o00); o01=sigf(o01); o10=sigf(o10); o11=sigf(o11); }
            else if (epi==4){ o00=decay_fn(o00); o01=decay_fn(o01); o10=decay_fn(o10); o11=decay_fn(o11); }
            *(float2*)(C + (size_t)row*N + col)     = make_float2(o00,o01);
            *(float2*)(C + (size_t)(row+8)*N + col) = make_float2(o10,o11);
        }
    }
}

__global__ __launch_bounds__(256) void gemm_nt_tf32(
    const float* __restrict__ A, int lda, const float* __restrict__ B,
    const float* __restrict__ bias, float* __restrict__ C, int N, int K, int epi)
{
    gemm_body(A, lda, B, bias, C, N, K, epi);
}

// batched stage-2 LoRA GEMMs (blockIdx.z selects)
__global__ __launch_bounds__(256) void gemm_stage2(
    const float* __restrict__ h1, const float* __restrict__ B2,
    const float* __restrict__ w0, const float* __restrict__ a0,
    const float* __restrict__ v0,
    float* __restrict__ wdec, float* __restrict__ iclr,
    float* __restrict__ vsig, float* __restrict__ gate)
{
    const int z = blockIdx.z;
    if (z==0)      gemm_body(h1+0,   512, B2+OFF_W, w0,      wdec, Cn,  96, 4);
    else if (z==1) gemm_body(h1+96,  512, B2+OFF_A, a0,      iclr, Cn,  96, 3);
    else if (z==2) gemm_body(h1+192, 512, B2+OFF_V, v0,      vsig, Cn,  64, 3);
    else           gemm_body(h1+256, 512, B2+OFF_G, nullptr, gate, Cn, 256, 0);
}

// cvt-copy: y=0 -> x, y=1 -> o_w  (pre-truncate to tf32)
__global__ void cvt_copy(const float* __restrict__ x, const float* __restrict__ ow,
                         float* __restrict__ xc, float* __restrict__ owc)
{
    const float* src = blockIdx.y ? ow : x;
    float* dst = blockIdx.y ? owc : xc;
    size_t idx = ((size_t)blockIdx.x*1024 + threadIdx.x)*4;
    float4 v = *(const float4*)(src + idx);
    v.x=f2tf32f(v.x); v.y=f2tf32f(v.y); v.z=f2tf32f(v.z); v.w=f2tf32f(v.w);
    *(float4*)(dst + idx) = v;
}

// pack fused B = [q_w ; k_w ; v_w ; wcatT] rows (tf32-truncated), and fused bias
__global__ void pack_B(const float* __restrict__ q_w, const float* __restrict__ k_w,
                       const float* __restrict__ v_w,
                       const float* __restrict__ w1, const float* __restrict__ a1,
                       const float* __restrict__ v1, const float* __restrict__ g1,
                       const float* __restrict__ q_b, const float* __restrict__ k_b,
                       const float* __restrict__ v_b,
                       float* __restrict__ Bout, float* __restrict__ biasOut)
{
    int row = blockIdx.x;
    for (int col = threadIdx.x; col < Cn; col += blockDim.x){
        float v;
        if (row < 2048)       v = q_w[(size_t)row*Cn + col];
        else if (row < 2560)  v = k_w[(size_t)(row-2048)*Cn + col];
        else if (row < 3072)  v = v_w[(size_t)(row-2560)*Cn + col];
        else {
            int c = row - 3072;
            if      (c < 96)  v = w1[(size_t)col*96  + c];
            else if (c < 192) v = a1[(size_t)col*96  + (c-96)];
            else if (c < 256) v = v1[(size_t)col*64  + (c-192)];
            else              v = g1[(size_t)col*256 + (c-256)];
        }
        Bout[(size_t)row*Cn + col] = f2tf32f(v);
    }
    if (threadIdx.x == 0){
        float bv = 0.f;
        if (row < 2048)      bv = q_b[row];
        else if (row < 2560) bv = k_b[row-2048];
        else if (row < 3072) bv = v_b[row-2560];
        biasOut[row] = bv;
    }
}

// transpose-pack stage-2 weights (tf32-truncated)
__global__ void pack_T2(const float* __restrict__ w2, const float* __restrict__ a2,
                        const float* __restrict__ v2, const float* __restrict__ g2,
                        float* __restrict__ out)
{
    int n = blockIdx.x, which = blockIdx.y, k = threadIdx.x;
    if (which==0){ if (k<96)  out[OFF_W + (size_t)n*96  + k] = f2tf32f(w2[(size_t)k*Cn + n]); }
    else if (which==1){ if (k<96)  out[OFF_A + (size_t)n*96  + k] = f2tf32f(a2[(size_t)k*Cn + n]); }
    else if (which==2){ if (k<64)  out[OFF_V + (size_t)n*64  + k] = f2tf32f(v2[(size_t)k*Cn + n]); }
    else              { if (k<256) out[OFF_G + (size_t)n*256 + k] = f2tf32f(g2[(size_t)k*Cn + n]); }
}

// pack + activate stage-2 A: [tanh(w)|a|v|sigmoid(g)] widths 96|96|64|256 (tf32-truncated)
__global__ void h1act_kernel(const float* __restrict__ qkvh, float* __restrict__ out)
{
    int row = blockIdx.x, c = threadIdx.x;
    float v = qkvh[(size_t)row*Nfused + 3072 + c];
    if (c < 96)       v = tanhf(v);
    else if (c >= 256) v = sigf(v);
    out[(size_t)row*512 + c] = f2tf32f(v);
}

// rope r/k, GQA repeat, kk normalize, k_final, v_final, ab = kk*iclr
__global__ __launch_bounds__(256) void prep_kernel(
    const float* __restrict__ qkvh,
    const float* __restrict__ iclr, const float* __restrict__ vsig, const float* __restrict__ vfirst,
    const float* __restrict__ cosb, const float* __restrict__ sinb,
    const float* __restrict__ k_k, const float* __restrict__ k_a,
    float* __restrict__ rrot, float* __restrict__ kkout, float* __restrict__ about,
    float* __restrict__ kfin, float* __restrict__ vfin)
{
    int wid = (blockIdx.x*blockDim.x + threadIdx.x) >> 5;
    int l = threadIdx.x & 31;
    int t = wid >> 5, h = wid & 31;
    int d0 = l, d1 = l+32;
    float c0 = cosb[t*64+d0], c1 = cosb[t*64+d1];
    float s0 = sinb[t*64+d0], s1 = sinb[t*64+d1];
    int base = t*Cn + h*64;
    int rbase = t*Nfused + h*64;
    int kbase = t*Nfused + 2048 + (h>>2)*64;
    int vbase = t*Nfused + 2560 + (h>>2)*64;
    float r0 = qkvh[rbase+d0], r1 = qkvh[rbase+d1];
    rrot[base+d0] = r0*c0 - r1*s0;
    rrot[base+d1] = r1*c1 + r0*s1;
    float k0 = qkvh[kbase+d0], k1 = qkvh[kbase+d1];
    float kr0 = k0*c0 - k1*s0, kr1 = k1*c1 + k0*s1;
    float m0 = kr0 * k_k[h*64+d0], m1 = kr1 * k_k[h*64+d1];
    float ss = m0*m0 + m1*m1;
    #pragma unroll
    for (int o=16;o>0;o>>=1) ss += __shfl_xor_sync(0xffffffffu, ss, o);
    float inv = 1.0f / fmaxf(sqrtf(ss), 1e-12f);
    float kk0 = m0*inv, kk1 = m1*inv;
    kkout[base+d0] = kk0; kkout[base+d1] = kk1;
    float ic0 = iclr[base+d0], ic1 = iclr[base+d1];
    about[base+d0] = kk0*ic0; about[base+d1] = kk1*ic1;
    kfin[base+d0] = kr0 * (1.0f + (ic0-1.0f)*k_a[h*64+d0]);
    kfin[base+d1] = kr1 * (1.0f + (ic1-1.0f)*k_a[h*64+d1]);
    float v0v = qkvh[vbase+d0], v1v = qkvh[vbase+d1];
    vfin[base+d0] = v0v + (vfirst[base+d0]-v0v)*vsig[base+d0];
    vfin[base+d1] = v1v + (vfirst[base+d1]-v1v)*vsig[base+d1];
}

// scan v5: 64 CTAs x 128 threads; each thread runs TWO independent chains
// (rows i and i+16) sharing the column streams -> ILP hides shfl/LDS latency.
// ring: 5 slots x 2 steps; per step [w|kk|ab|kf|rr](64 each) + vf(32) = 352 floats
__global__ __launch_bounds__(128) void scan_kernel(
    const float* __restrict__ wdec, const float* __restrict__ kkb,
    const float* __restrict__ abb,  const float* __restrict__ kf,
    const float* __restrict__ vf,   const float* __restrict__ rr,
    const float* __restrict__ s_in, float* __restrict__ yout, float* __restrict__ s_out)
{
    __shared__ float ring[5*704];
    const int b = blockIdx.x, h = b >> 1, half = b & 1;
    const int tid = threadIdx.x, rl = tid >> 3, sub = tid & 7;   // rl 0..15
    const int iA = half*32 + rl, iB = iA + 16, cb = sub*8;
    const int voffA = h*64 + iA, voffB = h*64 + iB;

    // producers: 80 threads for 5 streams x 16 chunks, 8 for vf (32 rows)
    const float* src = nullptr;
    int dloc = 0;
    if (tid < 80){
        int s = tid >> 4, col16 = (tid & 15)*4;
        const float* bases[5] = {wdec, kkb, abb, kf, rr};
        src = bases[s] + h*64 + col16;
        dloc = s*64 + col16;
    } else if (tid < 88){
        int j2 = tid - 80;
        src = vf + h*64 + half*32 + j2*4;
        dloc = 320 + j2*4;
    }
    const unsigned smbase = (unsigned)__cvta_generic_to_shared(ring);

    for (int s=0; s<4; s++){
        if (src){
            CP16(smbase + (s*704 +       dloc)*4, src + (size_t)(2*s  )*Cn);
            CP16(smbase + (s*704 + 352 + dloc)*4, src + (size_t)(2*s+1)*Cn);
        }
        CPCOMMIT();
    }

    float SA[8], SB[8];
    {
        const float4* spA = (const float4*)(s_in + (size_t)(h*64 + iA)*64 + cb);
        const float4* spB = (const float4*)(s_in + (size_t)(h*64 + iB)*64 + cb);
        float4 a=spA[0], c=spA[1], e=spB[0], g=spB[1];
        SA[0]=a.x;SA[1]=a.y;SA[2]=a.z;SA[3]=a.w;SA[4]=c.x;SA[5]=c.y;SA[6]=c.z;SA[7]=c.w;
        SB[0]=e.x;SB[1]=e.y;SB[2]=e.z;SB[3]=e.w;SB[4]=g.x;SB[5]=g.y;SB[6]=g.z;SB[7]=g.w;
    }

    CPWAIT(3);
    __syncthreads();
    float dA, dB;
    {
        const float* K0 = ring + 64 + cb;
        float a0=0.f,a1=0.f,b0=0.f,b1=0.f;
        #pragma unroll
        for (int q2=0;q2<4;q2++){
            a0 = fmaf(SA[q2], K0[q2], a0); a1 = fmaf(SA[q2+4], K0[q2+4], a1);
            b0 = fmaf(SB[q2], K0[q2], b0); b1 = fmaf(SB[q2+4], K0[q2+4], b1);
        }
        dA = a0+a1; dB = b0+b1;
        dA += __shfl_xor_sync(0xffffffffu, dA, 1);
        dB += __shfl_xor_sync(0xffffffffu, dB, 1);
        dA += __shfl_xor_sync(0xffffffffu, dA, 2);
        dB += __shfl_xor_sync(0xffffffffu, dB, 2);
        dA += __shfl_xor_sync(0xffffffffu, dA, 4);
        dB += __shfl_xor_sync(0xffffffffu, dB, 4);
    }

    for (int j=0; j<Tn/2; j++){
        CPWAIT(2);
        __syncthreads();
        {
            const int ws = ((j+4)%5)*704;
            if (src){
                CP16(smbase + (ws +       dloc)*4, src + (size_t)(2*j+8)*Cn);
                CP16(smbase + (ws + 352 + dloc)*4, src + (size_t)(2*j+9)*Cn);
            }
            CPCOMMIT();
        }
        const int s0 = (j%5)*704, s1 = ((j+1)%5)*704;
        #pragma unroll
        for (int d2=0; d2<2; d2++){
            const float* P  = ring + s0 + d2*352;
            const float* Kn = ring + (d2==0 ? (s0 + 352 + 64) : (s1 + 64)) + cb;
            float4 w0=((const float4*)(P+  0+cb))[0], w1=((const float4*)(P+  0+cb))[1];
            float4 a0=((const float4*)(P+128+cb))[0], a1=((const float4*)(P+128+cb))[1];
            float4 f0=((const float4*)(P+192+cb))[0], f1=((const float4*)(P+192+cb))[1];
            float4 r0=((const float4*)(P+256+cb))[0], r1=((const float4*)(P+256+cb))[1];
            float4 n0=((const float4*)Kn)[0],         n1=((const float4*)Kn)[1];
            const float viA = P[320 + rl];
            const float viB = P[336 + rl];
            float w[8]={w0.x,w0.y,w0.z,w0.w,w1.x,w1.y,w1.z,w1.w};
            float ab[8]={a0.x,a0.y,a0.z,a0.w,a1.x,a1.y,a1.z,a1.w};
            float fv[8]={f0.x,f0.y,f0.z,f0.w,f1.x,f1.y,f1.z,f1.w};
            float rv[8]={r0.x,r0.y,r0.z,r0.w,r1.x,r1.y,r1.z,r1.w};
            float kn[8]={n0.x,n0.y,n0.z,n0.w,n1.x,n1.y,n1.z,n1.w};

            float dnA0=0.f,dnA1=0.f,yA0=0.f,yA1=0.f;
            float dnB0=0.f,dnB1=0.f,yB0=0.f,yB1=0.f;
            #pragma unroll
            for (int q2=0;q2<8;q2++){
                float unA = fmaf(SA[q2], w[q2], viA*fv[q2]);
                float unB = fmaf(SB[q2], w[q2], viB*fv[q2]);
                SA[q2] = fmaf(-dA, ab[q2], unA);
                SB[q2] = fmaf(-dB, ab[q2], unB);
                if (q2<4){
                    dnA0 = fmaf(SA[q2], kn[q2], dnA0); yA0 = fmaf(SA[q2], rv[q2], yA0);
                    dnB0 = fmaf(SB[q2], kn[q2], dnB0); yB0 = fmaf(SB[q2], rv[q2], yB0);
                } else {
                    dnA1 = fmaf(SA[q2], kn[q2], dnA1); yA1 = fmaf(SA[q2], rv[q2], yA1);
                    dnB1 = fmaf(SB[q2], kn[q2], dnB1); yB1 = fmaf(SB[q2], rv[q2], yB1);
                }
            }
            float dnA = dnA0+dnA1, yvA = yA0+yA1;
            float dnB = dnB0+dnB1, yvB = yB0+yB1;
            dnA += __shfl_xor_sync(0xffffffffu, dnA, 1);
            dnB += __shfl_xor_sync(0xffffffffu, dnB, 1);
            yvA += __shfl_xor_sync(0xffffffffu, yvA, 1);
            yvB += __shfl_xor_sync(0xffffffffu, yvB, 1);
            dnA += __shfl_xor_sync(0xffffffffu, dnA, 2);
            dnB += __shfl_xor_sync(0xffffffffu, dnB, 2);
            yvA += __shfl_xor_sync(0xffffffffu, yvA, 2);
            yvB += __shfl_xor_sync(0xffffffffu, yvB, 2);
            dnA += __shfl_xor_sync(0xffffffffu, dnA, 4);
            dnB += __shfl_xor_sync(0xffffffffu, dnB, 4);
            yvA += __shfl_xor_sync(0xffffffffu, yvA, 4);
            yvB += __shfl_xor_sync(0xffffffffu, yvB, 4);
            if (sub==0){
                yout[(size_t)(2*j+d2)*Cn + voffA] = yvA;
                yout[(size_t)(2*j+d2)*Cn + voffB] = yvB;
            }
            dA = dnA; dB = dnB;
        }
    }
    float4* soA = (float4*)(s_out + (size_t)(h*64+iA)*64 + cb);
    float4* soB = (float4*)(s_out + (size_t)(h*64+iB)*64 + cb);
    soA[0] = make_float4(SA[0],SA[1],SA[2],SA[3]);
    soA[1] = make_float4(SA[4],SA[5],SA[6],SA[7]);
    soB[0] = make_float4(SB[0],SB[1],SB[2],SB[3]);
    soB[1] = make_float4(SB[4],SB[5],SB[6],SB[7]);
}

// groupnorm + ln + bonus + gate (z written tf32-truncated for o-GEMM)
__global__ __launch_bounds__(256) void post_kernel(
    const float* __restrict__ y, const float* __restrict__ rrot,
    const float* __restrict__ kfin, const float* __restrict__ vfin,
    const float* __restrict__ gate, const float* __restrict__ r_k,
    const float* __restrict__ ln_w, const float* __restrict__ ln_b,
    float* __restrict__ z)
{
    int wid = (blockIdx.x*blockDim.x + threadIdx.x) >> 5;
    int l = threadIdx.x & 31;
    int t = wid >> 5, h = wid & 31;
    int base = t*Cn + h*64;
    int d0 = l, d1 = l+32;
    float y0 = y[base+d0], y1 = y[base+d1];
    float s = y0+y1, sq = y0*y0 + y1*y1;
    float r0 = rrot[base+d0], r1 = rrot[base+d1];
    float dot = r0*kfin[base+d0]*r_k[h*64+d0] + r1*kfin[base+d1]*r_k[h*64+d1];
    #pragma unroll
    for (int o=16;o>0;o>>=1){
        s   += __shfl_xor_sync(0xffffffffu, s, o);
        sq  += __shfl_xor_sync(0xffffffffu, sq, o);
        dot += __shfl_xor_sync(0xffffffffu, dot, o);
    }
    float mu = s * (1.0f/64.0f);
    float var = sq * (1.0f/64.0f) - mu*mu;
    float rstd = rsqrtf(var + 6.4e-4f);
    float n0 = (y0-mu)*rstd*ln_w[h*64+d0] + ln_b[h*64+d0];
    float n1 = (y1-mu)*rstd*ln_w[h*64+d1] + ln_b[h*64+d1];
    z[base+d0] = f2tf32f((n0 + dot*vfin[base+d0]) * gate[base+d0]);
    z[base+d1] = f2tf32f((n1 + dot*vfin[base+d1]) * gate[base+d1]);
}

extern "C" void kernel_launch(void* const* d_in, const int* in_sizes, int n_in,
                              void* d_out, int out_size) {
    const float* x       = (const float*)d_in[0];
    const float* wkv_in  = (const float*)d_in[1];
    const float* v_first = (const float*)d_in[2];
    const float* cosb    = (const float*)d_in[3];
    const float* sinb    = (const float*)d_in[4];
    const float* w0      = (const float*)d_in[5];
    const float* w1      = (const float*)d_in[6];
    const float* w2      = (const float*)d_in[7];
    const float* a0      = (const float*)d_in[8];
    const float* a1      = (const float*)d_in[9];
    const float* a2      = (const float*)d_in[10];
    const float* v0      = (const float*)d_in[11];
    const float* v1      = (const float*)d_in[12];
    const float* v2      = (const float*)d_in[13];
    const float* g1      = (const float*)d_in[14];
    const float* g2      = (const float*)d_in[15];
    const float* k_k     = (const float*)d_in[16];
    const float* k_a     = (const float*)d_in[17];
    const float* r_k     = (const float*)d_in[18];
    const float* q_w     = (const float*)d_in[19];
    const float* q_b     = (const float*)d_in[20];
    const float* k_w     = (const float*)d_in[21];
    const float* k_b     = (const float*)d_in[22];
    const float* v_w     = (const float*)d_in[23];
    const float* v_b     = (const float*)d_in[24];
    const float* o_w     = (const float*)d_in[25];
    const float* ln_w    = (const float*)d_in[26];
    const float* ln_b    = (const float*)d_in[27];

    float* out   = (float*)d_out;
    float* s_out = out + (size_t)Tn*Cn;
    float* vf_out = s_out + 32*64*64;

    float *p_bigB, *p_bigBias, *p_B2, *p_h1act, *p_xc, *p_owc, *p_qkvh;
    float *p_wdec, *p_iclr, *p_ab, *p_vsig, *p_gate;
    float *p_rrot, *p_kfin, *p_vfin, *p_kk, *p_y, *p_z;
    cudaGetSymbolAddress((void**)&p_bigB, g_bigB);
    cudaGetSymbolAddress((void**)&p_bigBias, g_bigBias);
    cudaGetSymbolAddress((void**)&p_B2, g_B2);
    cudaGetSymbolAddress((void**)&p_h1act, g_h1act);
    cudaGetSymbolAddress((void**)&p_xc, g_xc);
    cudaGetSymbolAddress((void**)&p_owc, g_owc);
    cudaGetSymbolAddress((void**)&p_qkvh, g_qkvh);
    cudaGetSymbolAddress((void**)&p_wdec, g_wdec);
    cudaGetSymbolAddress((void**)&p_iclr, g_iclr);
    cudaGetSymbolAddress((void**)&p_ab, g_ab);
    cudaGetSymbolAddress((void**)&p_vsig, g_vsig);
    cudaGetSymbolAddress((void**)&p_gate, g_gate);
    cudaGetSymbolAddress((void**)&p_rrot, g_rrot);
    cudaGetSymbolAddress((void**)&p_kfin, g_kfin);
    cudaGetSymbolAddress((void**)&p_vfin, g_vfin);
    cudaGetSymbolAddress((void**)&p_kk, g_kk);
    cudaGetSymbolAddress((void**)&p_y, g_y);
    cudaGetSymbolAddress((void**)&p_z, g_z);

    cvt_copy<<<dim3(1024,2),1024>>>(x, o_w, p_xc, p_owc);
    pack_B<<<Nfused,512>>>(q_w, k_w, v_w, w1, a1, v1, g1, q_b, k_b, v_b,
                           p_bigB, p_bigBias);
    pack_T2<<<dim3(2048,4),256>>>(w2, a2, v2, g2, p_B2);
    gemm_nt_tf32<<<dim3(28,16),256>>>(p_xc, Cn, p_bigB, p_bigBias, p_qkvh, Nfused, Cn, 0);
    h1act_kernel<<<2048,512>>>(p_qkvh, p_h1act);
    gemm_stage2<<<dim3(16,16,4),256>>>(p_h1act, p_B2, w0, a0, v0,
                                       p_wdec, p_iclr, p_vsig, p_gate);
    prep_kernel<<<8192,256>>>(p_qkvh, p_iclr, p_vsig, v_first, cosb, sinb,
                              k_k, k_a, p_rrot, p_kk, p_ab, p_kfin, p_vfin);
    scan_kernel<<<64,128>>>(p_wdec, p_kk, p_ab, p_kfin, p_vfin, p_rrot,
                            wkv_in, p_y, s_out);
    post_kernel<<<8192,256>>>(p_y, p_rrot, p_kfin, p_vfin, p_gate, r_k, ln_w, ln_b, p_z);
    gemm_nt_tf32<<<dim3(16,16),256>>>(p_z, Cn, p_owc, nullptr, out, Cn, Cn, 0);
    cudaMemcpyAsync(vf_out, v_first, (size_t)Tn*Cn*sizeof(float),
                    cudaMemcpyDeviceToDevice, 0);
}

// round 11
// speedup vs baseline: 1.7669x; 1.7669x over previous
#include <cuda_runtime.h>
#include <cuda_bf16.h>
#include <math.h>

#define Tn   2048
#define Cn   2048
#define Nfused 3584

#define OFF_W 0
#define OFF_A (2048*96)
#define OFF_V (OFF_A + 2048*96)
#define OFF_G (OFF_V + 2048*64)

// scratch (device globals zero-initialized; scanned streams padded +16 rows)
__device__ float g_bigB[Nfused*Cn];
__device__ float g_bigBias[Nfused];
__device__ float g_B2[2048*512];
__device__ float g_h1act[Tn*512];
__device__ float g_xc[Tn*Cn];
__device__ float g_owc[Cn*Cn];
__device__ float g_qkvh[Tn*Nfused];
__device__ float g_wdec[(Tn+16)*Cn];
__device__ float g_iclr[Tn*Cn];
__device__ float g_ab  [(Tn+16)*Cn];
__device__ float g_vsig[Tn*Cn];
__device__ float g_gate[Tn*Cn];
__device__ float g_rrot[(Tn+16)*Cn];
__device__ float g_kfin[(Tn+16)*Cn];
__device__ float g_vfin[(Tn+16)*Cn];
__device__ float g_kk  [(Tn+16)*Cn];
__device__ float g_y[Tn*Cn];
__device__ float g_z[Tn*Cn];

__device__ __forceinline__ float sigf(float x){ return 1.0f/(1.0f + expf(-x)); }
__device__ __forceinline__ float decay_fn(float v){
    float nv = -v;
    float sp = (nv > 20.0f) ? nv : log1pf(expf(nv));
    return expf(-expf(-sp - 0.5f));
}
__device__ __forceinline__ float f2tf32f(float f){
    unsigned u;
    asm("cvt.rna.tf32.f32 %0, %1;" : "=r"(u) : "f"(f));
    return __uint_as_float(u);
}

#define CP16(sm, gp) asm volatile("cp.async.cg.shared.global [%0], [%1], 16;\n" :: "r"(sm), "l"(gp) : "memory")
#define CPCOMMIT()   asm volatile("cp.async.commit_group;\n" ::)
#define CPWAIT(n)    asm volatile("cp.async.wait_group %0;\n" :: "n"(n) : "memory")

__device__ __forceinline__ int SW(int row, int col){
    return row*16 + (col ^ (4*((row>>1)&3)));
}

// ---------------- pipelined TF32 GEMM body (operands pre-truncated to tf32) ----------------
// epi: 0 none, 3 sigmoid(c+bias), 4 decay(c+bias)
__device__ __forceinline__ void gemm_body(
    const float* __restrict__ A, int lda, const float* __restrict__ B,
    const float* __restrict__ bias, float* __restrict__ C, int N, int K, int epi)
{
    __shared__ float As[3][128*16];
    __shared__ float Bs[3][128*16];
    const int m0 = blockIdx.y*128, n0 = blockIdx.x*128;
    const int tid = threadIdx.x;
    const int wid = tid>>5, lane = tid&31;
    const int wm = (wid>>1)*32, wn = (wid&1)*64;
    const int r = lane>>2, q = lane&3;

    const int row0 = tid>>2, c40 = (tid&3)*4;
    const int row1 = row0 + 64;
    const float* Ag = A + (size_t)m0*lda;
    const float* Bg = B + (size_t)n0*K;
    const size_t a0off = (size_t)row0*lda + c40;
    const size_t a1off = (size_t)row1*lda + c40;
    const size_t b0off = (size_t)row0*K + c40;
    const size_t b1off = (size_t)row1*K + c40;

    float acc[2][8][4];
    #pragma unroll
    for (int i=0;i<2;i++)
        #pragma unroll
        for (int j=0;j<8;j++)
            #pragma unroll
            for (int c=0;c<4;c++) acc[i][j][c]=0.f;

    const int niter = K/16;
    #pragma unroll
    for (int p=0;p<2;p++){
        unsigned sa = (unsigned)__cvta_generic_to_shared(&As[p][0]);
        unsigned sb = (unsigned)__cvta_generic_to_shared(&Bs[p][0]);
        CP16(sa + SW(row0,c40)*4, Ag + p*16 + a0off);
        CP16(sa + SW(row1,c40)*4, Ag + p*16 + a1off);
        CP16(sb + SW(row0,c40)*4, Bg + p*16 + b0off);
        CP16(sb + SW(row1,c40)*4, Bg + p*16 + b1off);
        CPCOMMIT();
    }

    for (int it=0; it<niter; it++){
        const int nx = it+2;
        if (nx < niter){
            const int buf = nx%3;
            unsigned sa = (unsigned)__cvta_generic_to_shared(&As[buf][0]);
            unsigned sb = (unsigned)__cvta_generic_to_shared(&Bs[buf][0]);
            CP16(sa + SW(row0,c40)*4, Ag + nx*16 + a0off);
            CP16(sa + SW(row1,c40)*4, Ag + nx*16 + a1off);
            CP16(sb + SW(row0,c40)*4, Bg + nx*16 + b0off);
            CP16(sb + SW(row1,c40)*4, Bg + nx*16 + b1off);
        }
        CPCOMMIT();
        CPWAIT(2);
        __syncthreads();
        const float* as = As[it%3];
        const float* bs = Bs[it%3];
        #pragma unroll
        for (int ks=0; ks<2; ks++){
            const int kk = ks*8;
            unsigned a[2][4], b[8][2];
            #pragma unroll
            for (int mt=0;mt<2;mt++){
                const int row = wm + mt*16;
                a[mt][0]=__float_as_uint(as[SW(row+r,  kk+q  )]);
                a[mt][1]=__float_as_uint(as[SW(row+r+8,kk+q  )]);
                a[mt][2]=__float_as_uint(as[SW(row+r,  kk+q+4)]);
                a[mt][3]=__float_as_uint(as[SW(row+r+8,kk+q+4)]);
            }
            #pragma unroll
            for (int nt=0;nt<8;nt++){
                const int col = wn + nt*8;
                b[nt][0]=__float_as_uint(bs[SW(col+r, kk+q  )]);
                b[nt][1]=__float_as_uint(bs[SW(col+r, kk+q+4)]);
            }
            #pragma unroll
            for (int mt=0;mt<2;mt++){
                #pragma unroll
                for (int nt=0;nt<8;nt++){
                    asm volatile(
                        "mma.sync.aligned.m16n8k8.row.col.f32.tf32.tf32.f32 "
                        "{%0,%1,%2,%3}, {%4,%5,%6,%7}, {%8,%9}, {%0,%1,%2,%3};"
                        : "+f"(acc[mt][nt][0]),"+f"(acc[mt][nt][1]),
                          "+f"(acc[mt][nt][2]),"+f"(acc[mt][nt][3])
                        : "r"(a[mt][0]),"r"(a[mt][1]),"r"(a[mt][2]),"r"(a[mt][3]),
                          "r"(b[nt][0]),"r"(b[nt][1]));
                }
            }
        }
        __syncthreads();
    }
    #pragma unroll
    for (int mt=0;mt<2;mt++){
        #pragma unroll
        for (int nt=0;nt<8;nt++){
            int row = m0 + wm + mt*16 + r;
            int col = n0 + wn + nt*8 + q*2;
            float bx=0.f, by=0.f;
            if (bias){ bx=bias[col]; by=bias[col+1]; }
            float o00=acc[mt][nt][0]+bx, o01=acc[mt][nt][1]+by;
            float o10=acc[mt][nt][2]+bx, o11=acc[mt][nt][3]+by;
            if (epi==3){ o00=sigf(o00); o01=sigf(o01); o10=sigf(o10); o11=sigf(o11); }
            else if (epi==4){ o00=decay_fn(o00); o01=decay_fn(o01); o10=decay_fn(o10); o11=decay_fn(o11); }
            *(float2*)(C + (size_t)row*N + col)     = make_float2(o00,o01);
            *(float2*)(C + (size_t)(row+8)*N + col) = make_float2(o10,o11);
        }
    }
}

__global__ __launch_bounds__(256) void gemm_nt_tf32(
    const float* __restrict__ A, int lda, const float* __restrict__ B,
    const float* __restrict__ bias, float* __restrict__ C, int N, int K, int epi)
{
    gemm_body(A, lda, B, bias, C, N, K, epi);
}

// batched stage-2 LoRA GEMMs (blockIdx.z selects)
__global__ __launch_bounds__(256) void gemm_stage2(
    const float* __restrict__ h1, const float* __restrict__ B2,
    const float* __restrict__ w0, const float* __restrict__ a0,
    const float* __restrict__ v0,
    float* __restrict__ wdec, float* __restrict__ iclr,
    float* __restrict__ vsig, float* __restrict__ gate)
{
    const int z = blockIdx.z;
    if (z==0)      gemm_body(h1+0,   512, B2+OFF_W, w0,      wdec, Cn,  96, 4);
    else if (z==1) gemm_body(h1+96,  512, B2+OFF_A, a0,      iclr, Cn,  96, 3);
    else if (z==2) gemm_body(h1+192, 512, B2+OFF_V, v0,      vsig, Cn,  64, 3);
    else           gemm_body(h1+256, 512, B2+OFF_G, nullptr, gate, Cn, 256, 0);
}

// cvt-copy: y=0 -> x, y=1 -> o_w  (pre-truncate to tf32)
__global__ void cvt_copy(const float* __restrict__ x, const float* __restrict__ ow,
                         float* __restrict__ xc, float* __restrict__ owc)
{
    const float* src = blockIdx.y ? ow : x;
    float* dst = blockIdx.y ? owc : xc;
    size_t idx = ((size_t)blockIdx.x*1024 + threadIdx.x)*4;
    float4 v = *(const float4*)(src + idx);
    v.x=f2tf32f(v.x); v.y=f2tf32f(v.y); v.z=f2tf32f(v.z); v.w=f2tf32f(v.w);
    *(float4*)(dst + idx) = v;
}

// pack fused B = [q_w ; k_w ; v_w ; wcatT] rows (tf32-truncated), and fused bias
__global__ void pack_B(const float* __restrict__ q_w, const float* __restrict__ k_w,
                       const float* __restrict__ v_w,
                       const float* __restrict__ w1, const float* __restrict__ a1,
                       const float* __restrict__ v1, const float* __restrict__ g1,
                       const float* __restrict__ q_b, const float* __restrict__ k_b,
                       const float* __restrict__ v_b,
                       float* __restrict__ Bout, float* __restrict__ biasOut)
{
    int row = blockIdx.x;
    for (int col = threadIdx.x; col < Cn; col += blockDim.x){
        float v;
        if (row < 2048)       v = q_w[(size_t)row*Cn + col];
        else if (row < 2560)  v = k_w[(size_t)(row-2048)*Cn + col];
        else if (row < 3072)  v = v_w[(size_t)(row-2560)*Cn + col];
        else {
            int c = row - 3072;
            if      (c < 96)  v = w1[(size_t)col*96  + c];
            else if (c < 192) v = a1[(size_t)col*96  + (c-96)];
            else if (c < 256) v = v1[(size_t)col*64  + (c-192)];
            else              v = g1[(size_t)col*256 + (c-256)];
        }
        Bout[(size_t)row*Cn + col] = f2tf32f(v);
    }
    if (threadIdx.x == 0){
        float bv = 0.f;
        if (row < 2048)      bv = q_b[row];
        else if (row < 2560) bv = k_b[row-2048];
        else if (row < 3072) bv = v_b[row-2560];
        biasOut[row] = bv;
    }
}

// transpose-pack stage-2 weights (tf32-truncated)
__global__ void pack_T2(const float* __restrict__ w2, const float* __restrict__ a2,
                        const float* __restrict__ v2, const float* __restrict__ g2,
                        float* __restrict__ out)
{
    int n = blockIdx.x, which = blockIdx.y, k = threadIdx.x;
    if (which==0){ if (k<96)  out[OFF_W + (size_t)n*96  + k] = f2tf32f(w2[(size_t)k*Cn + n]); }
    else if (which==1){ if (k<96)  out[OFF_A + (size_t)n*96  + k] = f2tf32f(a2[(size_t)k*Cn + n]); }
    else if (which==2){ if (k<64)  out[OFF_V + (size_t)n*64  + k] = f2tf32f(v2[(size_t)k*Cn + n]); }
    else              { if (k<256) out[OFF_G + (size_t)n*256 + k] = f2tf32f(g2[(size_t)k*Cn + n]); }
}

// pack + activate stage-2 A: [tanh(w)|a|v|sigmoid(g)] widths 96|96|64|256 (tf32-truncated)
__global__ void h1act_kernel(const float* __restrict__ qkvh, float* __restrict__ out)
{
    int row = blockIdx.x, c = threadIdx.x;
    float v = qkvh[(size_t)row*Nfused + 3072 + c];
    if (c < 96)       v = tanhf(v);
    else if (c >= 256) v = sigf(v);
    out[(size_t)row*512 + c] = f2tf32f(v);
}

// rope r/k, GQA repeat, kk normalize, k_final, v_final, ab = kk*iclr
__global__ __launch_bounds__(256) void prep_kernel(
    const float* __restrict__ qkvh,
    const float* __restrict__ iclr, const float* __restrict__ vsig, const float* __restrict__ vfirst,
    const float* __restrict__ cosb, const float* __restrict__ sinb,
    const float* __restrict__ k_k, const float* __restrict__ k_a,
    float* __restrict__ rrot, float* __restrict__ kkout, float* __restrict__ about,
    float* __restrict__ kfin, float* __restrict__ vfin)
{
    int wid = (blockIdx.x*blockDim.x + threadIdx.x) >> 5;
    int l = threadIdx.x & 31;
    int t = wid >> 5, h = wid & 31;
    int d0 = l, d1 = l+32;
    float c0 = cosb[t*64+d0], c1 = cosb[t*64+d1];
    float s0 = sinb[t*64+d0], s1 = sinb[t*64+d1];
    int base = t*Cn + h*64;
    int rbase = t*Nfused + h*64;
    int kbase = t*Nfused + 2048 + (h>>2)*64;
    int vbase = t*Nfused + 2560 + (h>>2)*64;
    float r0 = qkvh[rbase+d0], r1 = qkvh[rbase+d1];
    rrot[base+d0] = r0*c0 - r1*s0;
    rrot[base+d1] = r1*c1 + r0*s1;
    float k0 = qkvh[kbase+d0], k1 = qkvh[kbase+d1];
    float kr0 = k0*c0 - k1*s0, kr1 = k1*c1 + k0*s1;
    float m0 = kr0 * k_k[h*64+d0], m1 = kr1 * k_k[h*64+d1];
    float ss = m0*m0 + m1*m1;
    #pragma unroll
    for (int o=16;o>0;o>>=1) ss += __shfl_xor_sync(0xffffffffu, ss, o);
    float inv = 1.0f / fmaxf(sqrtf(ss), 1e-12f);
    float kk0 = m0*inv, kk1 = m1*inv;
    kkout[base+d0] = kk0; kkout[base+d1] = kk1;
    float ic0 = iclr[base+d0], ic1 = iclr[base+d1];
    about[base+d0] = kk0*ic0; about[base+d1] = kk1*ic1;
    kfin[base+d0] = kr0 * (1.0f + (ic0-1.0f)*k_a[h*64+d0]);
    kfin[base+d1] = kr1 * (1.0f + (ic1-1.0f)*k_a[h*64+d1]);
    float v0v = qkvh[vbase+d0], v1v = qkvh[vbase+d1];
    vfin[base+d0] = v0v + (vfirst[base+d0]-v0v)*vsig[base+d0];
    vfin[base+d1] = v1v + (vfirst[base+d1]-v1v)*vsig[base+d1];
}

// scan v6: R8 structure (128 CTAs x 128 threads, 1 chain/thread), ring of
// 5 slots x FOUR timesteps (sync machinery halved vs v3).
// per step layout: [w(64)|kk(64)|ab(64)|kf(64)|rr(64)|vf(16)] = 336 floats; slot = 1344
__global__ __launch_bounds__(128) void scan_kernel(
    const float* __restrict__ wdec, const float* __restrict__ kkb,
    const float* __restrict__ abb,  const float* __restrict__ kf,
    const float* __restrict__ vf,   const float* __restrict__ rr,
    const float* __restrict__ s_in, float* __restrict__ yout, float* __restrict__ s_out)
{
    __shared__ float ring[5*1344];
    const int b = blockIdx.x, h = b >> 2, rbk = b & 3;
    const int tid = threadIdx.x, rl = tid >> 3, sub = tid & 7;
    const int i = rbk*16 + rl, cb = sub*8;
    const int voff = h*64 + i;

    // producers: 80 threads for 5 streams x 16 chunks, 4 for vf (16 rows)
    const float* src = nullptr;
    int dloc = 0;
    if (tid < 80){
        int s = tid >> 4, col16 = (tid & 15)*4;
        const float* bases[5] = {wdec, kkb, abb, kf, rr};
        src = bases[s] + h*64 + col16;
        dloc = s*64 + col16;
    } else if (tid < 84){
        int j2 = tid - 80;
        src = vf + h*64 + rbk*16 + j2*4;
        dloc = 320 + j2*4;
    }
    const unsigned smbase = (unsigned)__cvta_generic_to_shared(ring);

    // prologue: fill slots 0..3 (steps 0..15), one commit per slot
    for (int s=0; s<4; s++){
        if (src){
            #pragma unroll
            for (int st=0; st<4; st++)
                CP16(smbase + (s*1344 + st*336 + dloc)*4, src + (size_t)(4*s+st)*Cn);
        }
        CPCOMMIT();
    }

    float S[8];
    {
        const float4* sp = (const float4*)(s_in + (size_t)(h*64 + i)*64 + cb);
        float4 a = sp[0], c = sp[1];
        S[0]=a.x;S[1]=a.y;S[2]=a.z;S[3]=a.w;S[4]=c.x;S[5]=c.y;S[6]=c.z;S[7]=c.w;
    }

    CPWAIT(3);
    __syncthreads();
    float d;
    {
        const float* K0 = ring + 64 + cb;   // kk step 0
        float t0=0.f, t1=0.f;
        #pragma unroll
        for (int q2=0;q2<4;q2++){ t0 = fmaf(S[q2], K0[q2], t0); t1 = fmaf(S[q2+4], K0[q2+4], t1); }
        d = t0 + t1;
        d += __shfl_xor_sync(0xffffffffu, d, 1);
        d += __shfl_xor_sync(0xffffffffu, d, 2);
        d += __shfl_xor_sync(0xffffffffu, d, 4);
    }

    for (int j=0; j<Tn/4; j++){
        CPWAIT(2);                 // slots j, j+1 complete
        __syncthreads();           // iter j-1 reads done -> safe to overwrite slot (j+4)%5
        {
            const int ws = ((j+4)%5)*1344;
            if (src){
                #pragma unroll
                for (int st=0; st<4; st++)
                    CP16(smbase + (ws + st*336 + dloc)*4, src + (size_t)(4*j+16+st)*Cn);
            }
            CPCOMMIT();
        }
        const int s0 = (j%5)*1344, s1 = ((j+1)%5)*1344;
        #pragma unroll
        for (int d2=0; d2<4; d2++){
            const float* P  = ring + s0 + d2*336;
            const float* Kn = ring + (d2<3 ? (s0 + (d2+1)*336 + 64) : (s1 + 64)) + cb;
            float4 w0=((const float4*)(P+  0+cb))[0], w1=((const float4*)(P+  0+cb))[1];
            float4 a0=((const float4*)(P+128+cb))[0], a1=((const float4*)(P+128+cb))[1];
            float4 f0=((const float4*)(P+192+cb))[0], f1=((const float4*)(P+192+cb))[1];
            float4 r0=((const float4*)(P+256+cb))[0], r1=((const float4*)(P+256+cb))[1];
            float4 n0=((const float4*)Kn)[0],         n1=((const float4*)Kn)[1];
            const float vi = P[320 + rl];
            float w[8]={w0.x,w0.y,w0.z,w0.w,w1.x,w1.y,w1.z,w1.w};
            float ab[8]={a0.x,a0.y,a0.z,a0.w,a1.x,a1.y,a1.z,a1.w};
            float fv[8]={f0.x,f0.y,f0.z,f0.w,f1.x,f1.y,f1.z,f1.w};
            float rv[8]={r0.x,r0.y,r0.z,r0.w,r1.x,r1.y,r1.z,r1.w};
            float kn[8]={n0.x,n0.y,n0.z,n0.w,n1.x,n1.y,n1.z,n1.w};

            float dn0=0.f,dn1=0.f,y0=0.f,y1=0.f;
            #pragma unroll
            for (int q2=0;q2<8;q2++){
                float un = fmaf(S[q2], w[q2], vi*fv[q2]);
                S[q2] = fmaf(-d, ab[q2], un);
                if (q2<4){ dn0 = fmaf(S[q2], kn[q2], dn0); y0 = fmaf(S[q2], rv[q2], y0); }
                else     { dn1 = fmaf(S[q2], kn[q2], dn1); y1 = fmaf(S[q2], rv[q2], y1); }
            }
            float dn = dn0+dn1, yv = y0+y1;
            dn += __shfl_xor_sync(0xffffffffu, dn, 1);
            yv += __shfl_xor_sync(0xffffffffu, yv, 1);
            dn += __shfl_xor_sync(0xffffffffu, dn, 2);
            yv += __shfl_xor_sync(0xffffffffu, yv, 2);
            dn += __shfl_xor_sync(0xffffffffu, dn, 4);
            yv += __shfl_xor_sync(0xffffffffu, yv, 4);
            if (sub==0) yout[(size_t)(4*j+d2)*Cn + voff] = yv;
            d = dn;
        }
    }
    float4* so = (float4*)(s_out + (size_t)(h*64+i)*64 + cb);
    so[0] = make_float4(S[0],S[1],S[2],S[3]);
    so[1] = make_float4(S[4],S[5],S[6],S[7]);
}

// groupnorm + ln + bonus + gate (z written tf32-truncated for o-GEMM)
__global__ __launch_bounds__(256) void post_kernel(
    const float* __restrict__ y, const float* __restrict__ rrot,
    const float* __restrict__ kfin, const float* __restrict__ vfin,
    const float* __restrict__ gate, const float* __restrict__ r_k,
    const float* __restrict__ ln_w, const float* __restrict__ ln_b,
    float* __restrict__ z)
{
    int wid = (blockIdx.x*blockDim.x + threadIdx.x) >> 5;
    int l = threadIdx.x & 31;
    int t = wid >> 5, h = wid & 31;
    int base = t*Cn + h*64;
    int d0 = l, d1 = l+32;
    float y0 = y[base+d0], y1 = y[base+d1];
    float s = y0+y1, sq = y0*y0 + y1*y1;
    float r0 = rrot[base+d0], r1 = rrot[base+d1];
    float dot = r0*kfin[base+d0]*r_k[h*64+d0] + r1*kfin[base+d1]*r_k[h*64+d1];
    #pragma unroll
    for (int o=16;o>0;o>>=1){
        s   += __shfl_xor_sync(0xffffffffu, s, o);
        sq  += __shfl_xor_sync(0xffffffffu, sq, o);
        dot += __shfl_xor_sync(0xffffffffu, dot, o);
    }
    float mu = s * (1.0f/64.0f);
    float var = sq * (1.0f/64.0f) - mu*mu;
    float rstd = rsqrtf(var + 6.4e-4f);
    float n0 = (y0-mu)*rstd*ln_w[h*64+d0] + ln_b[h*64+d0];
    float n1 = (y1-mu)*rstd*ln_w[h*64+d1] + ln_b[h*64+d1];
    z[base+d0] = f2tf32f((n0 + dot*vfin[base+d0]) * gate[base+d0]);
    z[base+d1] = f2tf32f((n1 + dot*vfin[base+d1]) * gate[base+d1]);
}

extern "C" void kernel_launch(void* const* d_in, const int* in_sizes, int n_in,
                              void* d_out, int out_size) {
    const float* x       = (const float*)d_in[0];
    const float* wkv_in  = (const float*)d_in[1];
    const float* v_first = (const float*)d_in[2];
    const float* cosb    = (const float*)d_in[3];
    const float* sinb    = (const float*)d_in[4];
    const float* w0      = (const float*)d_in[5];
    const float* w1      = (const float*)d_in[6];
    const float* w2      = (const float*)d_in[7];
    const float* a0      = (const float*)d_in[8];
    const float* a1      = (const float*)d_in[9];
    const float* a2      = (const float*)d_in[10];
    const float* v0      = (const float*)d_in[11];
    const float* v1      = (const float*)d_in[12];
    const float* v2      = (const float*)d_in[13];
    const float* g1      = (const float*)d_in[14];
    const float* g2      = (const float*)d_in[15];
    const float* k_k     = (const float*)d_in[16];
    const float* k_a     = (const float*)d_in[17];
    const float* r_k     = (const float*)d_in[18];
    const float* q_w     = (const float*)d_in[19];
    const float* q_b     = (const float*)d_in[20];
    const float* k_w     = (const float*)d_in[21];
    const float* k_b     = (const float*)d_in[22];
    const float* v_w     = (const float*)d_in[23];
    const float* v_b     = (const float*)d_in[24];
    const float* o_w     = (const float*)d_in[25];
    const float* ln_w    = (const float*)d_in[26];
    const float* ln_b    = (const float*)d_in[27];

    float* out   = (float*)d_out;
    float* s_out = out + (size_t)Tn*Cn;
    float* vf_out = s_out + 32*64*64;

    float *p_bigB, *p_bigBias, *p_B2, *p_h1act, *p_xc, *p_owc, *p_qkvh;
    float *p_wdec, *p_iclr, *p_ab, *p_vsig, *p_gate;
    float *p_rrot, *p_kfin, *p_vfin, *p_kk, *p_y, *p_z;
    cudaGetSymbolAddress((void**)&p_bigB, g_bigB);
    cudaGetSymbolAddress((void**)&p_bigBias, g_bigBias);
    cudaGetSymbolAddress((void**)&p_B2, g_B2);
    cudaGetSymbolAddress((void**)&p_h1act, g_h1act);
    cudaGetSymbolAddress((void**)&p_xc, g_xc);
    cudaGetSymbolAddress((void**)&p_owc, g_owc);
    cudaGetSymbolAddress((void**)&p_qkvh, g_qkvh);
    cudaGetSymbolAddress((void**)&p_wdec, g_wdec);
    cudaGetSymbolAddress((void**)&p_iclr, g_iclr);
    cudaGetSymbolAddress((void**)&p_ab, g_ab);
    cudaGetSymbolAddress((void**)&p_vsig, g_vsig);
    cudaGetSymbolAddress((void**)&p_gate, g_gate);
    cudaGetSymbolAddress((void**)&p_rrot, g_rrot);
    cudaGetSymbolAddress((void**)&p_kfin, g_kfin);
    cudaGetSymbolAddress((void**)&p_vfin, g_vfin);
    cudaGetSymbolAddress((void**)&p_kk, g_kk);
    cudaGetSymbolAddress((void**)&p_y, g_y);
    cudaGetSymbolAddress((void**)&p_z, g_z);

    cvt_copy<<<dim3(1024,2),1024>>>(x, o_w, p_xc, p_owc);
    pack_B<<<Nfused,512>>>(q_w, k_w, v_w, w1, a1, v1, g1, q_b, k_b, v_b,
                           p_bigB, p_bigBias);
    pack_T2<<<dim3(2048,4),256>>>(w2, a2, v2, g2, p_B2);
    gemm_nt_tf32<<<dim3(28,16),256>>>(p_xc, Cn, p_bigB, p_bigBias, p_qkvh, Nfused, Cn, 0);
    h1act_kernel<<<2048,512>>>(p_qkvh, p_h1act);
    gemm_stage2<<<dim3(16,16,4),256>>>(p_h1act, p_B2, w0, a0, v0,
                                       p_wdec, p_iclr, p_vsig, p_gate);
    prep_kernel<<<8192,256>>>(p_qkvh, p_iclr, p_vsig, v_first, cosb, sinb,
                              k_k, k_a, p_rrot, p_kk, p_ab, p_kfin, p_vfin);
    scan_kernel<<<128,128>>>(p_wdec, p_kk, p_ab, p_kfin, p_vfin, p_rrot,
                             wkv_in, p_y, s_out);
    post_kernel<<<8192,256>>>(p_y, p_rrot, p_kfin, p_vfin, p_gate, r_k, ln_w, ln_b, p_z);
    gemm_nt_tf32<<<dim3(16,16),256>>>(p_z, Cn, p_owc, nullptr, out, Cn, Cn, 0);
    cudaMemcpyAsync(vf_out, v_first, (size_t)Tn*Cn*sizeof(float),
                    cudaMemcpyDeviceToDevice, 0);
}

// round 12
// speedup vs baseline: 1.8088x; 1.0237x over previous
#include <cuda_runtime.h>
#include <cuda_bf16.h>
#include <math.h>

#define Tn   2048
#define Cn   2048
#define Nfused 3584

#define OFF_W 0
#define OFF_A (2048*96)
#define OFF_V (OFF_A + 2048*96)
#define OFF_G (OFF_V + 2048*64)

#define GEMM_SMEM (4*128*16*4*2)   // 4 stages x (A+B) x 128x16 floats = 64 KB

// scratch (device globals zero-initialized; scanned streams padded +16 rows)
__device__ float g_bigB[Nfused*Cn];
__device__ float g_bigBias[Nfused];
__device__ float g_B2[2048*512];
__device__ float g_h1act[Tn*512];
__device__ float g_xc[Tn*Cn];
__device__ float g_owc[Cn*Cn];
__device__ float g_qkvh[Tn*Nfused];
__device__ float g_wdec[(Tn+16)*Cn];
__device__ float g_iclr[Tn*Cn];
__device__ float g_ab  [(Tn+16)*Cn];
__device__ float g_vsig[Tn*Cn];
__device__ float g_gate[Tn*Cn];
__device__ float g_rrot[(Tn+16)*Cn];
__device__ float g_kfin[(Tn+16)*Cn];
__device__ float g_vfin[(Tn+16)*Cn];
__device__ float g_kk  [(Tn+16)*Cn];
__device__ float g_y[Tn*Cn];
__device__ float g_z[Tn*Cn];

__device__ __forceinline__ float sigf(float x){ return 1.0f/(1.0f + expf(-x)); }
__device__ __forceinline__ float decay_fn(float v){
    float nv = -v;
    float sp = (nv > 20.0f) ? nv : log1pf(expf(nv));
    return expf(-expf(-sp - 0.5f));
}
__device__ __forceinline__ float f2tf32f(float f){
    unsigned u;
    asm("cvt.rna.tf32.f32 %0, %1;" : "=r"(u) : "f"(f));
    return __uint_as_float(u);
}

#define CP16(sm, gp) asm volatile("cp.async.cg.shared.global [%0], [%1], 16;\n" :: "r"(sm), "l"(gp) : "memory")
#define CPCOMMIT()   asm volatile("cp.async.commit_group;\n" ::)
#define CPWAIT(n)    asm volatile("cp.async.wait_group %0;\n" :: "n"(n) : "memory")

__device__ __forceinline__ int SW(int row, int col){
    return row*16 + (col ^ (4*((row>>1)&3)));
}

// ---------------- pipelined TF32 GEMM body: 4-stage ring, ONE bar per k-tile ----------------
// operands pre-truncated to tf32; epi: 0 none, 3 sigmoid(c+bias), 4 decay(c+bias)
__device__ __forceinline__ void gemm_body(
    const float* __restrict__ A, int lda, const float* __restrict__ B,
    const float* __restrict__ bias, float* __restrict__ C, int N, int K, int epi)
{
    extern __shared__ float smem_dyn[];
    float* Asm = smem_dyn;                 // 4 stages x 128*16
    float* Bsm = smem_dyn + 4*128*16;      // 4 stages x 128*16
    const int m0 = blockIdx.y*128, n0 = blockIdx.x*128;
    const int tid = threadIdx.x;
    const int wid = tid>>5, lane = tid&31;
    const int wm = (wid>>1)*32, wn = (wid&1)*64;
    const int r = lane>>2, q = lane&3;

    const int row0 = tid>>2, c40 = (tid&3)*4;
    const int row1 = row0 + 64;
    const float* Ag = A + (size_t)m0*lda;
    const float* Bg = B + (size_t)n0*K;
    const size_t a0off = (size_t)row0*lda + c40;
    const size_t a1off = (size_t)row1*lda + c40;
    const size_t b0off = (size_t)row0*K + c40;
    const size_t b1off = (size_t)row1*K + c40;

    float acc[2][8][4];
    #pragma unroll
    for (int i=0;i<2;i++)
        #pragma unroll
        for (int j=0;j<8;j++)
            #pragma unroll
            for (int c=0;c<4;c++) acc[i][j][c]=0.f;

    const int niter = K/16;
    // prologue: stages 0,1,2
    #pragma unroll
    for (int p=0;p<3;p++){
        unsigned sa = (unsigned)__cvta_generic_to_shared(Asm + p*128*16);
        unsigned sb = (unsigned)__cvta_generic_to_shared(Bsm + p*128*16);
        CP16(sa + SW(row0,c40)*4, Ag + p*16 + a0off);
        CP16(sa + SW(row1,c40)*4, Ag + p*16 + a1off);
        CP16(sb + SW(row0,c40)*4, Bg + p*16 + b0off);
        CP16(sb + SW(row1,c40)*4, Bg + p*16 + b1off);
        CPCOMMIT();
    }

    for (int it=0; it<niter; it++){
        CPWAIT(2);                // stage it complete
        __syncthreads();          // all warps done reading stage (it+3)%4's buffer (from it-1)
        const int nx = it+3;
        if (nx < niter){
            const int buf = nx&3;
            unsigned sa = (unsigned)__cvta_generic_to_shared(Asm + buf*128*16);
            unsigned sb = (unsigned)__cvta_generic_to_shared(Bsm + buf*128*16);
            CP16(sa + SW(row0,c40)*4, Ag + nx*16 + a0off);
            CP16(sa + SW(row1,c40)*4, Ag + nx*16 + a1off);
            CP16(sb + SW(row0,c40)*4, Bg + nx*16 + b0off);
            CP16(sb + SW(row1,c40)*4, Bg + nx*16 + b1off);
        }
        CPCOMMIT();
        const float* as = Asm + (it&3)*128*16;
        const float* bs = Bsm + (it&3)*128*16;
        #pragma unroll
        for (int ks=0; ks<2; ks++){
            const int kk = ks*8;
            unsigned a[2][4], b[8][2];
            #pragma unroll
            for (int mt=0;mt<2;mt++){
                const int row = wm + mt*16;
                a[mt][0]=__float_as_uint(as[SW(row+r,  kk+q  )]);
                a[mt][1]=__float_as_uint(as[SW(row+r+8,kk+q  )]);
                a[mt][2]=__float_as_uint(as[SW(row+r,  kk+q+4)]);
                a[mt][3]=__float_as_uint(as[SW(row+r+8,kk+q+4)]);
            }
            #pragma unroll
            for (int nt=0;nt<8;nt++){
                const int col = wn + nt*8;
                b[nt][0]=__float_as_uint(bs[SW(col+r, kk+q  )]);
                b[nt][1]=__float_as_uint(bs[SW(col+r, kk+q+4)]);
            }
            #pragma unroll
            for (int mt=0;mt<2;mt++){
                #pragma unroll
                for (int nt=0;nt<8;nt++){
                    asm volatile(
                        "mma.sync.aligned.m16n8k8.row.col.f32.tf32.tf32.f32 "
                        "{%0,%1,%2,%3}, {%4,%5,%6,%7}, {%8,%9}, {%0,%1,%2,%3};"
                        : "+f"(acc[mt][nt][0]),"+f"(acc[mt][nt][1]),
                          "+f"(acc[mt][nt][2]),"+f"(acc[mt][nt][3])
                        : "r"(a[mt][0]),"r"(a[mt][1]),"r"(a[mt][2]),"r"(a[mt][3]),
                          "r"(b[nt][0]),"r"(b[nt][1]));
                }
            }
        }
    }
    #pragma unroll
    for (int mt=0;mt<2;mt++){
        #pragma unroll
        for (int nt=0;nt<8;nt++){
            int row = m0 + wm + mt*16 + r;
            int col = n0 + wn + nt*8 + q*2;
            float bx=0.f, by=0.f;
            if (bias){ bx=bias[col]; by=bias[col+1]; }
            float o00=acc[mt][nt][0]+bx, o01=acc[mt][nt][1]+by;
            float o10=acc[mt][nt][2]+bx, o11=acc[mt][nt][3]+by;
            if (epi==3){ o00=sigf(o00); o01=sigf(o01); o10=sigf(o10); o11=sigf(o11); }
            else if (epi==4){ o00=decay_fn(o00); o01=decay_fn(o01); o10=decay_fn(o10); o11=decay_fn(o11); }
            *(float2*)(C + (size_t)row*N + col)     = make_float2(o00,o01);
            *(float2*)(C + (size_t)(row+8)*N + col) = make_float2(o10,o11);
        }
    }
}

__global__ __launch_bounds__(256) void gemm_nt_tf32(
    const float* __restrict__ A, int lda, const float* __restrict__ B,
    const float* __restrict__ bias, float* __restrict__ C, int N, int K, int epi)
{
    gemm_body(A, lda, B, bias, C, N, K, epi);
}

// batched stage-2 LoRA GEMMs (blockIdx.z selects)
__global__ __launch_bounds__(256) void gemm_stage2(
    const float* __restrict__ h1, const float* __restrict__ B2,
    const float* __restrict__ w0, const float* __restrict__ a0,
    const float* __restrict__ v0,
    float* __restrict__ wdec, float* __restrict__ iclr,
    float* __restrict__ vsig, float* __restrict__ gate)
{
    const int z = blockIdx.z;
    if (z==0)      gemm_body(h1+0,   512, B2+OFF_W, w0,      wdec, Cn,  96, 4);
    else if (z==1) gemm_body(h1+96,  512, B2+OFF_A, a0,      iclr, Cn,  96, 3);
    else if (z==2) gemm_body(h1+192, 512, B2+OFF_V, v0,      vsig, Cn,  64, 3);
    else           gemm_body(h1+256, 512, B2+OFF_G, nullptr, gate, Cn, 256, 0);
}

// cvt-copy: y=0 -> x, y=1 -> o_w  (pre-truncate to tf32)
__global__ void cvt_copy(const float* __restrict__ x, const float* __restrict__ ow,
                         float* __restrict__ xc, float* __restrict__ owc)
{
    const float* src = blockIdx.y ? ow : x;
    float* dst = blockIdx.y ? owc : xc;
    size_t idx = ((size_t)blockIdx.x*1024 + threadIdx.x)*4;
    float4 v = *(const float4*)(src + idx);
    v.x=f2tf32f(v.x); v.y=f2tf32f(v.y); v.z=f2tf32f(v.z); v.w=f2tf32f(v.w);
    *(float4*)(dst + idx) = v;
}

// pack fused B = [q_w ; k_w ; v_w ; wcatT] rows (tf32-truncated), and fused bias
__global__ void pack_B(const float* __restrict__ q_w, const float* __restrict__ k_w,
                       const float* __restrict__ v_w,
                       const float* __restrict__ w1, const float* __restrict__ a1,
                       const float* __restrict__ v1, const float* __restrict__ g1,
                       const float* __restrict__ q_b, const float* __restrict__ k_b,
                       const float* __restrict__ v_b,
                       float* __restrict__ Bout, float* __restrict__ biasOut)
{
    int row = blockIdx.x;
    for (int col = threadIdx.x; col < Cn; col += blockDim.x){
        float v;
        if (row < 2048)       v = q_w[(size_t)row*Cn + col];
        else if (row < 2560)  v = k_w[(size_t)(row-2048)*Cn + col];
        else if (row < 3072)  v = v_w[(size_t)(row-2560)*Cn + col];
        else {
            int c = row - 3072;
            if      (c < 96)  v = w1[(size_t)col*96  + c];
            else if (c < 192) v = a1[(size_t)col*96  + (c-96)];
            else if (c < 256) v = v1[(size_t)col*64  + (c-192)];
            else              v = g1[(size_t)col*256 + (c-256)];
        }
        Bout[(size_t)row*Cn + col] = f2tf32f(v);
    }
    if (threadIdx.x == 0){
        float bv = 0.f;
        if (row < 2048)      bv = q_b[row];
        else if (row < 2560) bv = k_b[row-2048];
        else if (row < 3072) bv = v_b[row-2560];
        biasOut[row] = bv;
    }
}

// transpose-pack stage-2 weights (tf32-truncated)
__global__ void pack_T2(const float* __restrict__ w2, const float* __restrict__ a2,
                        const float* __restrict__ v2, const float* __restrict__ g2,
                        float* __restrict__ out)
{
    int n = blockIdx.x, which = blockIdx.y, k = threadIdx.x;
    if (which==0){ if (k<96)  out[OFF_W + (size_t)n*96  + k] = f2tf32f(w2[(size_t)k*Cn + n]); }
    else if (which==1){ if (k<96)  out[OFF_A + (size_t)n*96  + k] = f2tf32f(a2[(size_t)k*Cn + n]); }
    else if (which==2){ if (k<64)  out[OFF_V + (size_t)n*64  + k] = f2tf32f(v2[(size_t)k*Cn + n]); }
    else              { if (k<256) out[OFF_G + (size_t)n*256 + k] = f2tf32f(g2[(size_t)k*Cn + n]); }
}

// pack + activate stage-2 A: [tanh(w)|a|v|sigmoid(g)] widths 96|96|64|256 (tf32-truncated)
__global__ void h1act_kernel(const float* __restrict__ qkvh, float* __restrict__ out)
{
    int row = blockIdx.x, c = threadIdx.x;
    float v = qkvh[(size_t)row*Nfused + 3072 + c];
    if (c < 96)       v = tanhf(v);
    else if (c >= 256) v = sigf(v);
    out[(size_t)row*512 + c] = f2tf32f(v);
}

// rope r/k, GQA repeat, kk normalize, k_final, v_final, ab = kk*iclr
__global__ __launch_bounds__(256) void prep_kernel(
    const float* __restrict__ qkvh,
    const float* __restrict__ iclr, const float* __restrict__ vsig, const float* __restrict__ vfirst,
    const float* __restrict__ cosb, const float* __restrict__ sinb,
    const float* __restrict__ k_k, const float* __restrict__ k_a,
    float* __restrict__ rrot, float* __restrict__ kkout, float* __restrict__ about,
    float* __restrict__ kfin, float* __restrict__ vfin)
{
    int wid = (blockIdx.x*blockDim.x + threadIdx.x) >> 5;
    int l = threadIdx.x & 31;
    int t = wid >> 5, h = wid & 31;
    int d0 = l, d1 = l+32;
    float c0 = cosb[t*64+d0], c1 = cosb[t*64+d1];
    float s0 = sinb[t*64+d0], s1 = sinb[t*64+d1];
    int base = t*Cn + h*64;
    int rbase = t*Nfused + h*64;
    int kbase = t*Nfused + 2048 + (h>>2)*64;
    int vbase = t*Nfused + 2560 + (h>>2)*64;
    float r0 = qkvh[rbase+d0], r1 = qkvh[rbase+d1];
    rrot[base+d0] = r0*c0 - r1*s0;
    rrot[base+d1] = r1*c1 + r0*s1;
    float k0 = qkvh[kbase+d0], k1 = qkvh[kbase+d1];
    float kr0 = k0*c0 - k1*s0, kr1 = k1*c1 + k0*s1;
    float m0 = kr0 * k_k[h*64+d0], m1 = kr1 * k_k[h*64+d1];
    float ss = m0*m0 + m1*m1;
    #pragma unroll
    for (int o=16;o>0;o>>=1) ss += __shfl_xor_sync(0xffffffffu, ss, o);
    float inv = 1.0f / fmaxf(sqrtf(ss), 1e-12f);
    float kk0 = m0*inv, kk1 = m1*inv;
    kkout[base+d0] = kk0; kkout[base+d1] = kk1;
    float ic0 = iclr[base+d0], ic1 = iclr[base+d1];
    about[base+d0] = kk0*ic0; about[base+d1] = kk1*ic1;
    kfin[base+d0] = kr0 * (1.0f + (ic0-1.0f)*k_a[h*64+d0]);
    kfin[base+d1] = kr1 * (1.0f + (ic1-1.0f)*k_a[h*64+d1]);
    float v0v = qkvh[vbase+d0], v1v = qkvh[vbase+d1];
    vfin[base+d0] = v0v + (vfirst[base+d0]-v0v)*vsig[base+d0];
    vfin[base+d1] = v1v + (vfirst[base+d1]-v1v)*vsig[base+d1];
}

// scan v6b: 128 CTAs x 128 threads, ring of 5 slots x 4 timesteps, wait_group 3
// per step layout: [w(64)|kk(64)|ab(64)|kf(64)|rr(64)|vf(16)] = 336 floats; slot = 1344
__global__ __launch_bounds__(128) void scan_kernel(
    const float* __restrict__ wdec, const float* __restrict__ kkb,
    const float* __restrict__ abb,  const float* __restrict__ kf,
    const float* __restrict__ vf,   const float* __restrict__ rr,
    const float* __restrict__ s_in, float* __restrict__ yout, float* __restrict__ s_out)
{
    __shared__ float ring[5*1344];
    const int b = blockIdx.x, h = b >> 2, rbk = b & 3;
    const int tid = threadIdx.x, rl = tid >> 3, sub = tid & 7;
    const int i = rbk*16 + rl, cb = sub*8;
    const int voff = h*64 + i;

    const float* src = nullptr;
    int dloc = 0;
    if (tid < 80){
        int s = tid >> 4, col16 = (tid & 15)*4;
        const float* bases[5] = {wdec, kkb, abb, kf, rr};
        src = bases[s] + h*64 + col16;
        dloc = s*64 + col16;
    } else if (tid < 84){
        int j2 = tid - 80;
        src = vf + h*64 + rbk*16 + j2*4;
        dloc = 320 + j2*4;
    }
    const unsigned smbase = (unsigned)__cvta_generic_to_shared(ring);

    for (int s=0; s<4; s++){
        if (src){
            #pragma unroll
            for (int st=0; st<4; st++)
                CP16(smbase + (s*1344 + st*336 + dloc)*4, src + (size_t)(4*s+st)*Cn);
        }
        CPCOMMIT();
    }

    float S[8];
    {
        const float4* sp = (const float4*)(s_in + (size_t)(h*64 + i)*64 + cb);
        float4 a = sp[0], c = sp[1];
        S[0]=a.x;S[1]=a.y;S[2]=a.z;S[3]=a.w;S[4]=c.x;S[5]=c.y;S[6]=c.z;S[7]=c.w;
    }

    CPWAIT(3);
    __syncthreads();
    float d;
    {
        const float* K0 = ring + 64 + cb;
        float t0=0.f, t1=0.f;
        #pragma unroll
        for (int q2=0;q2<4;q2++){ t0 = fmaf(S[q2], K0[q2], t0); t1 = fmaf(S[q2+4], K0[q2+4], t1); }
        d = t0 + t1;
        d += __shfl_xor_sync(0xffffffffu, d, 1);
        d += __shfl_xor_sync(0xffffffffu, d, 2);
        d += __shfl_xor_sync(0xffffffffu, d, 4);
    }

    for (int j=0; j<Tn/4; j++){
        CPWAIT(3);                 // slots j, j+1 complete (slot j+1's group issued 3 iters ago)
        __syncthreads();
        {
            const int ws = ((j+4)%5)*1344;
            if (src){
                #pragma unroll
                for (int st=0; st<4; st++)
                    CP16(smbase + (ws + st*336 + dloc)*4, src + (size_t)(4*j+16+st)*Cn);
            }
            CPCOMMIT();
        }
        const int s0 = (j%5)*1344, s1 = ((j+1)%5)*1344;
        #pragma unroll
        for (int d2=0; d2<4; d2++){
            const float* P  = ring + s0 + d2*336;
            const float* Kn = ring + (d2<3 ? (s0 + (d2+1)*336 + 64) : (s1 + 64)) + cb;
            float4 w0=((const float4*)(P+  0+cb))[0], w1=((const float4*)(P+  0+cb))[1];
            float4 a0=((const float4*)(P+128+cb))[0], a1=((const float4*)(P+128+cb))[1];
            float4 f0=((const float4*)(P+192+cb))[0], f1=((const float4*)(P+192+cb))[1];
            float4 r0=((const float4*)(P+256+cb))[0], r1=((const float4*)(P+256+cb))[1];
            float4 n0=((const float4*)Kn)[0],         n1=((const float4*)Kn)[1];
            const float vi = P[320 + rl];
            float w[8]={w0.x,w0.y,w0.z,w0.w,w1.x,w1.y,w1.z,w1.w};
            float ab[8]={a0.x,a0.y,a0.z,a0.w,a1.x,a1.y,a1.z,a1.w};
            float fv[8]={f0.x,f0.y,f0.z,f0.w,f1.x,f1.y,f1.z,f1.w};
            float rv[8]={r0.x,r0.y,r0.z,r0.w,r1.x,r1.y,r1.z,r1.w};
            float kn[8]={n0.x,n0.y,n0.z,n0.w,n1.x,n1.y,n1.z,n1.w};

            float dn0=0.f,dn1=0.f,y0=0.f,y1=0.f;
            #pragma unroll
            for (int q2=0;q2<8;q2++){
                float un = fmaf(S[q2], w[q2], vi*fv[q2]);
                S[q2] = fmaf(-d, ab[q2], un);
                if (q2<4){ dn0 = fmaf(S[q2], kn[q2], dn0); y0 = fmaf(S[q2], rv[q2], y0); }
                else     { dn1 = fmaf(S[q2], kn[q2], dn1); y1 = fmaf(S[q2], rv[q2], y1); }
            }
            float dn = dn0+dn1, yv = y0+y1;
            dn += __shfl_xor_sync(0xffffffffu, dn, 1);
            yv += __shfl_xor_sync(0xffffffffu, yv, 1);
            dn += __shfl_xor_sync(0xffffffffu, dn, 2);
            yv += __shfl_xor_sync(0xffffffffu, yv, 2);
            dn += __shfl_xor_sync(0xffffffffu, dn, 4);
            yv += __shfl_xor_sync(0xffffffffu, yv, 4);
            if (sub==0) yout[(size_t)(4*j+d2)*Cn + voff] = yv;
            d = dn;
        }
    }
    float4* so = (float4*)(s_out + (size_t)(h*64+i)*64 + cb);
    so[0] = make_float4(S[0],S[1],S[2],S[3]);
    so[1] = make_float4(S[4],S[5],S[6],S[7]);
}

// groupnorm + ln + bonus + gate (z written tf32-truncated for o-GEMM)
__global__ __launch_bounds__(256) void post_kernel(
    const float* __restrict__ y, const float* __restrict__ rrot,
    const float* __restrict__ kfin, const float* __restrict__ vfin,
    const float* __restrict__ gate, const float* __restrict__ r_k,
    const float* __restrict__ ln_w, const float* __restrict__ ln_b,
    float* __restrict__ z)
{
    int wid = (blockIdx.x*blockDim.x + threadIdx.x) >> 5;
    int l = threadIdx.x & 31;
    int t = wid >> 5, h = wid & 31;
    int base = t*Cn + h*64;
    int d0 = l, d1 = l+32;
    float y0 = y[base+d0], y1 = y[base+d1];
    float s = y0+y1, sq = y0*y0 + y1*y1;
    float r0 = rrot[base+d0], r1 = rrot[base+d1];
    float dot = r0*kfin[base+d0]*r_k[h*64+d0] + r1*kfin[base+d1]*r_k[h*64+d1];
    #pragma unroll
    for (int o=16;o>0;o>>=1){
        s   += __shfl_xor_sync(0xffffffffu, s, o);
        sq  += __shfl_xor_sync(0xffffffffu, sq, o);
        dot += __shfl_xor_sync(0xffffffffu, dot, o);
    }
    float mu = s * (1.0f/64.0f);
    float var = sq * (1.0f/64.0f) - mu*mu;
    float rstd = rsqrtf(var + 6.4e-4f);
    float n0 = (y0-mu)*rstd*ln_w[h*64+d0] + ln_b[h*64+d0];
    float n1 = (y1-mu)*rstd*ln_w[h*64+d1] + ln_b[h*64+d1];
    z[base+d0] = f2tf32f((n0 + dot*vfin[base+d0]) * gate[base+d0]);
    z[base+d1] = f2tf32f((n1 + dot*vfin[base+d1]) * gate[base+d1]);
}

extern "C" void kernel_launch(void* const* d_in, const int* in_sizes, int n_in,
                              void* d_out, int out_size) {
    const float* x       = (const float*)d_in[0];
    const float* wkv_in  = (const float*)d_in[1];
    const float* v_first = (const float*)d_in[2];
    const float* cosb    = (const float*)d_in[3];
    const float* sinb    = (const float*)d_in[4];
    const float* w0      = (const float*)d_in[5];
    const float* w1      = (const float*)d_in[6];
    const float* w2      = (const float*)d_in[7];
    const float* a0      = (const float*)d_in[8];
    const float* a1      = (const float*)d_in[9];
    const float* a2      = (const float*)d_in[10];
    const float* v0      = (const float*)d_in[11];
    const float* v1      = (const float*)d_in[12];
    const float* v2      = (const float*)d_in[13];
    const float* g1      = (const float*)d_in[14];
    const float* g2      = (const float*)d_in[15];
    const float* k_k     = (const float*)d_in[16];
    const float* k_a     = (const float*)d_in[17];
    const float* r_k     = (const float*)d_in[18];
    const float* q_w     = (const float*)d_in[19];
    const float* q_b     = (const float*)d_in[20];
    const float* k_w     = (const float*)d_in[21];
    const float* k_b     = (const float*)d_in[22];
    const float* v_w     = (const float*)d_in[23];
    const float* v_b     = (const float*)d_in[24];
    const float* o_w     = (const float*)d_in[25];
    const float* ln_w    = (const float*)d_in[26];
    const float* ln_b    = (const float*)d_in[27];

    float* out   = (float*)d_out;
    float* s_out = out + (size_t)Tn*Cn;
    float* vf_out = s_out + 32*64*64;

    float *p_bigB, *p_bigBias, *p_B2, *p_h1act, *p_xc, *p_owc, *p_qkvh;
    float *p_wdec, *p_iclr, *p_ab, *p_vsig, *p_gate;
    float *p_rrot, *p_kfin, *p_vfin, *p_kk, *p_y, *p_z;
    cudaGetSymbolAddress((void**)&p_bigB, g_bigB);
    cudaGetSymbolAddress((void**)&p_bigBias, g_bigBias);
    cudaGetSymbolAddress((void**)&p_B2, g_B2);
    cudaGetSymbolAddress((void**)&p_h1act, g_h1act);
    cudaGetSymbolAddress((void**)&p_xc, g_xc);
    cudaGetSymbolAddress((void**)&p_owc, g_owc);
    cudaGetSymbolAddress((void**)&p_qkvh, g_qkvh);
    cudaGetSymbolAddress((void**)&p_wdec, g_wdec);
    cudaGetSymbolAddress((void**)&p_iclr, g_iclr);
    cudaGetSymbolAddress((void**)&p_ab, g_ab);
    cudaGetSymbolAddress((void**)&p_vsig, g_vsig);
    cudaGetSymbolAddress((void**)&p_gate, g_gate);
    cudaGetSymbolAddress((void**)&p_rrot, g_rrot);
    cudaGetSymbolAddress((void**)&p_kfin, g_kfin);
    cudaGetSymbolAddress((void**)&p_vfin, g_vfin);
    cudaGetSymbolAddress((void**)&p_kk, g_kk);
    cudaGetSymbolAddress((void**)&p_y, g_y);
    cudaGetSymbolAddress((void**)&p_z, g_z);

    // opt-in to 64 KB dynamic smem for the GEMM kernels (immediate, capture-safe)
    cudaFuncSetAttribute(gemm_nt_tf32, cudaFuncAttributeMaxDynamicSharedMemorySize, GEMM_SMEM);
    cudaFuncSetAttribute(gemm_stage2,  cudaFuncAttributeMaxDynamicSharedMemorySize, GEMM_SMEM);

    cvt_copy<<<dim3(1024,2),1024>>>(x, o_w, p_xc, p_owc);
    pack_B<<<Nfused,512>>>(q_w, k_w, v_w, w1, a1, v1, g1, q_b, k_b, v_b,
                           p_bigB, p_bigBias);
    pack_T2<<<dim3(2048,4),256>>>(w2, a2, v2, g2, p_B2);
    gemm_nt_tf32<<<dim3(28,16),256,GEMM_SMEM>>>(p_xc, Cn, p_bigB, p_bigBias, p_qkvh, Nfused, Cn, 0);
    h1act_kernel<<<2048,512>>>(p_qkvh, p_h1act);
    gemm_stage2<<<dim3(16,16,4),256,GEMM_SMEM>>>(p_h1act, p_B2, w0, a0, v0,
                                                 p_wdec, p_iclr, p_vsig, p_gate);
    prep_kernel<<<8192,256>>>(p_qkvh, p_iclr, p_vsig, v_first, cosb, sinb,
                              k_k, k_a, p_rrot, p_kk, p_ab, p_kfin, p_vfin);
    scan_kernel<<<128,128>>>(p_wdec, p_kk, p_ab, p_kfin, p_vfin, p_rrot,
                             wkv_in, p_y, s_out);
    post_kernel<<<8192,256>>>(p_y, p_rrot, p_kfin, p_vfin, p_gate, r_k, ln_w, ln_b, p_z);
    gemm_nt_tf32<<<dim3(16,16),256,GEMM_SMEM>>>(p_z, Cn, p_owc, nullptr, out, Cn, Cn, 0);
    cudaMemcpyAsync(vf_out, v_first, (size_t)Tn*Cn*sizeof(float),
                    cudaMemcpyDeviceToDevice, 0);
}